// round 12
// baseline (speedup 1.0000x reference)
#include <cuda_runtime.h>
#include <cuda_bf16.h>

// out[n,c,k,l] = x[n,c,oh,ow] - xpad[n,c,oh+i,ow+j]; K=7, PAD=3
// x:(16,64,56,56) f32 -> out:(16,64,49,3136) f32.
//
// R11b: isolation test — R6 kernel (best, 96.1us) with the ONE untested
// store-path variable flipped: __stcs (evict-first) -> default .wb stores.
// Mechanism under test: L2-pooled dirty-line eviction vs prompt streaming
// drain for a 629MB pure write stream on B300 LTS/DRAM.
// Everything else byte-identical to R6.

#define PLANE   3136        // 56*56
#define TPITCH  64          // padded pitch (16B-aligned rows)
#define TROWS   62          // 56 + 2*3
#define NTHREADS 256
#define NGROUPS 784         // 3136 / 4 float4-groups per k

__global__ __launch_bounds__(NTHREADS, 1)
void Subtraction_68212670595965_kernel(const float* __restrict__ x,
                                       float* __restrict__ out) {
    __shared__ float tile[TROWS * TPITCH];   // 62*64*4 = 15872 B

    const int nc = blockIdx.x;               // n*64 + c, 0..1023
    const float* __restrict__ xin = x + (size_t)nc * PLANE;
    float* __restrict__ outb = out + (size_t)nc * 49 * PLANE;

    const int tid = threadIdx.x;

    // ---- Fused staging: halo zeros + interior vector loads, ONE barrier ----
    {
        float4 z = {0.f, 0.f, 0.f, 0.f};
        // top rows 0..2 and bottom rows 59..61 (each 64 floats = 16 float4)
        if (tid < 96) {
            const int half = tid / 48;               // 0=top, 1=bottom
            const int q    = tid - half * 48;        // 0..47
            const int row  = half ? (59 + q / 16) : (q / 16);
            reinterpret_cast<float4*>(&tile[row * TPITCH])[q & 15] = z;
        }
        // side halos: 56 rows * 8 cols (0..2, 59..63) = 448 scalars
        #pragma unroll 1
        for (int s = tid; s < 448; s += NTHREADS) {
            const int r  = s / 8;
            const int cc = s & 7;
            const int col = (cc < 3) ? cc : (56 + cc);
            tile[(r + 3) * TPITCH + col] = 0.0f;
        }
    }

    // interior fill: 56 rows x 14 float4 LDG.128, scattered STS (+3 halo).
    #pragma unroll 1
    for (int idx = tid; idx < 56 * 14; idx += NTHREADS) {
        const int r  = idx / 14;          // input row 0..55
        const int c4 = idx - r * 14;      // float4 index within row
        const float4 v = reinterpret_cast<const float4*>(xin + r * 56)[c4];
        float* dst = &tile[(r + 3) * TPITCH + 3 + c4 * 4];
        dst[0] = v.x; dst[1] = v.y; dst[2] = v.z; dst[3] = v.w;
    }
    __syncthreads();

    // ---- Store phase (default .wb stores; only diff vs R6) ----
    #pragma unroll 1
    for (int g = tid; g < NGROUPS; g += NTHREADS) {
        const int oh  = g / 14;
        const int ow4 = (g - oh * 14) * 4;          // 0,4,...,52

        const int cbase = (oh + 3) * TPITCH + ow4 + 3;
        const float c0 = tile[cbase + 0];
        const float c1 = tile[cbase + 1];
        const float c2 = tile[cbase + 2];
        const float c3 = tile[cbase + 3];

        float* __restrict__ op = outb + 4 * g;

        #pragma unroll
        for (int i = 0; i < 7; ++i) {
            const float4* rp =
                reinterpret_cast<const float4*>(&tile[(oh + i) * TPITCH + ow4]);
            const float4 a = rp[0];
            const float4 b = rp[1];
            const float4 cq = rp[2];
            const float r[12] = {a.x, a.y, a.z, a.w,
                                 b.x, b.y, b.z, b.w,
                                 cq.x, cq.y, cq.z, cq.w};
            #pragma unroll
            for (int j = 0; j < 7; ++j) {
                float4 o;
                o.x = c0 - r[j + 0];
                o.y = c1 - r[j + 1];
                o.z = c2 - r[j + 2];
                o.w = c3 - r[j + 3];
                *reinterpret_cast<float4*>(op + (i * 7 + j) * PLANE) = o;
            }
        }
    }
}

extern "C" void kernel_launch(void* const* d_in, const int* in_sizes, int n_in,
                              void* d_out, int out_size) {
    const float* x = (const float*)d_in[0];
    float* out = (float*)d_out;
    Subtraction_68212670595965_kernel<<<1024, NTHREADS>>>(x, out);
}

// round 13
// speedup vs baseline: 1.0514x; 1.0514x over previous
#include <cuda_runtime.h>
#include <cuda_bf16.h>

// out[n,c,k,l] = x[n,c,oh,ow] - xpad[n,c,oh+i,ow+j]; K=7, PAD=3
// x:(16,64,56,56) f32 -> out:(16,64,49,3136) f32.
//
// FINAL (R6 config, best 96.1us): DRAM-write-bound at ~6.7 TB/s effective
// (~84% of spec), the HBM write-turnaround ceiling for a pure store stream.
// Isolated-and-verified levers: STG.128 (win), .cs streaming hint (win,
// +4.5us vs .wb), fused 1-barrier prologue (win). Falsified: occupancy up
// (R3) / down (R9), staging prefetch (R8), .wb pooled eviction (R11b).
//
// Shape: 1024 CTAs (one per (n,c) plane) x 256 threads, 4 resident CTAs/SM.
// 62x64 padded SMEM tile; halo-zero fused with LDG.128 staging, one barrier;
// 49 st.global.cs.v4 per 4-pixel group, perfectly coalesced per warp.

#define PLANE   3136        // 56*56
#define TPITCH  64          // padded pitch (16B-aligned rows)
#define TROWS   62          // 56 + 2*3
#define NTHREADS 256
#define NGROUPS 784         // 3136 / 4 float4-groups per k

__global__ __launch_bounds__(NTHREADS, 1)
void Subtraction_68212670595965_kernel(const float* __restrict__ x,
                                       float* __restrict__ out) {
    __shared__ float tile[TROWS * TPITCH];   // 62*64*4 = 15872 B

    const int nc = blockIdx.x;               // n*64 + c, 0..1023
    const float* __restrict__ xin = x + (size_t)nc * PLANE;
    float* __restrict__ outb = out + (size_t)nc * 49 * PLANE;

    const int tid = threadIdx.x;

    // ---- Fused staging: halo zeros + interior vector loads, ONE barrier ----
    {
        float4 z = {0.f, 0.f, 0.f, 0.f};
        // top rows 0..2 and bottom rows 59..61 (each 64 floats = 16 float4)
        if (tid < 96) {
            const int half = tid / 48;               // 0=top, 1=bottom
            const int q    = tid - half * 48;        // 0..47
            const int row  = half ? (59 + q / 16) : (q / 16);
            reinterpret_cast<float4*>(&tile[row * TPITCH])[q & 15] = z;
        }
        // side halos: 56 rows * 8 cols (0..2, 59..63) = 448 scalars
        #pragma unroll 1
        for (int s = tid; s < 448; s += NTHREADS) {
            const int r  = s / 8;
            const int cc = s & 7;
            const int col = (cc < 3) ? cc : (56 + cc);
            tile[(r + 3) * TPITCH + col] = 0.0f;
        }
    }

    // interior fill: 56 rows x 14 float4 LDG.128, scattered STS (+3 halo).
    #pragma unroll 1
    for (int idx = tid; idx < 56 * 14; idx += NTHREADS) {
        const int r  = idx / 14;          // input row 0..55
        const int c4 = idx - r * 14;      // float4 index within row
        const float4 v = reinterpret_cast<const float4*>(xin + r * 56)[c4];
        float* dst = &tile[(r + 3) * TPITCH + 3 + c4 * 4];
        dst[0] = v.x; dst[1] = v.y; dst[2] = v.z; dst[3] = v.w;
    }
    __syncthreads();

    // ---- Store phase: 49 streaming STG.128 per 4-pixel group ----
    #pragma unroll 1
    for (int g = tid; g < NGROUPS; g += NTHREADS) {
        const int oh  = g / 14;
        const int ow4 = (g - oh * 14) * 4;          // 0,4,...,52

        const int cbase = (oh + 3) * TPITCH + ow4 + 3;
        const float c0 = tile[cbase + 0];
        const float c1 = tile[cbase + 1];
        const float c2 = tile[cbase + 2];
        const float c3 = tile[cbase + 3];

        float* __restrict__ op = outb + 4 * g;

        #pragma unroll
        for (int i = 0; i < 7; ++i) {
            const float4* rp =
                reinterpret_cast<const float4*>(&tile[(oh + i) * TPITCH + ow4]);
            const float4 a = rp[0];
            const float4 b = rp[1];
            const float4 cq = rp[2];
            const float r[12] = {a.x, a.y, a.z, a.w,
                                 b.x, b.y, b.z, b.w,
                                 cq.x, cq.y, cq.z, cq.w};
            #pragma unroll
            for (int j = 0; j < 7; ++j) {
                float4 o;
                o.x = c0 - r[j + 0];
                o.y = c1 - r[j + 1];
                o.z = c2 - r[j + 2];
                o.w = c3 - r[j + 3];
                __stcs(reinterpret_cast<float4*>(op + (i * 7 + j) * PLANE), o);
            }
        }
    }
}

extern "C" void kernel_launch(void* const* d_in, const int* in_sizes, int n_in,
                              void* d_out, int out_size) {
    const float* x = (const float*)d_in[0];
    float* out = (float*)d_out;
    Subtraction_68212670595965_kernel<<<1024, NTHREADS>>>(x, out);
}